// round 8
// baseline (speedup 1.0000x reference)
#include <cuda_runtime.h>
#include <cuda_bf16.h>

// VolumeSDF renderer: one warp per TWO rays, 4 samples per lane per ray.
// out[n] = sum_s T_s * (1 - exp(-tau_s + eps)) * color[n,s,:]
//   density = ALPHA * LaplaceCDF(-sdf; BETA)
//   tau_s   = density_s * delta_s,  delta = diff(depth), last = 1e10
//   T_s     = exp(-inclusive_cumsum(tau)_s)
//
// Two rays per warp: 10 independent LDG.128 front-batched (MLP=10) and two
// independent scan/exp chains (ILP=2) to hide memory + shfl latency.
// __launch_bounds__(256,4) grants a 64-reg budget so the batched loads can
// actually stay live (at 32 regs ptxas re-serializes them — R6 finding).

#define RENDER_ALPHA 10.0f
#define INV_BETA     20.0f      // 1 / 0.05
#define RENDER_EPS   1e-10f
#define FAR_DELTA    1e10f

__global__ __launch_bounds__(256, 4)
void volume_sdf_render_kernel(const float* __restrict__ sdf,
                              const float* __restrict__ color,
                              const float* __restrict__ depth,
                              float* __restrict__ out,
                              int N)
{
    const int gtid  = blockIdx.x * blockDim.x + threadIdx.x;
    const int warp  = gtid >> 5;
    const int lane  = threadIdx.x & 31;
    const int rayA  = warp * 2;
    const int rayB  = rayA + 1;
    if (rayA >= N) return;

    const int S = 128;
    const long long baseA  = (long long)rayA * S + lane * 4;
    const long long baseB  = baseA + S;
    const long long cbaseA = baseA * 3;
    const long long cbaseB = baseB * 3;

    // ---- Front-batch ALL global loads: 10x LDG.128 ----
    const float4 sA = *reinterpret_cast<const float4*>(sdf   + baseA);
    const float4 sB = *reinterpret_cast<const float4*>(sdf   + baseB);
    const float4 dA = *reinterpret_cast<const float4*>(depth + baseA);
    const float4 dB = *reinterpret_cast<const float4*>(depth + baseB);
    const float4 caA = *reinterpret_cast<const float4*>(color + cbaseA);
    const float4 cbA = *reinterpret_cast<const float4*>(color + cbaseA + 4);
    const float4 ccA = *reinterpret_cast<const float4*>(color + cbaseA + 8);
    const float4 caB = *reinterpret_cast<const float4*>(color + cbaseB);
    const float4 cbB = *reinterpret_cast<const float4*>(color + cbaseB + 4);
    const float4 ccB = *reinterpret_cast<const float4*>(color + cbaseB + 8);

    // Deltas: depth[4l+4] lives in the next lane's .x (per ray).
    const float dnA = __shfl_down_sync(0xffffffffu, dA.x, 1);
    const float dnB = __shfl_down_sync(0xffffffffu, dB.x, 1);

    float delA[4], delB[4];
    delA[0] = dA.y - dA.x;  delB[0] = dB.y - dB.x;
    delA[1] = dA.z - dA.y;  delB[1] = dB.z - dB.y;
    delA[2] = dA.w - dA.z;  delB[2] = dB.w - dB.z;
    delA[3] = (lane == 31) ? FAR_DELTA : (dnA - dA.w);
    delB[3] = (lane == 31) ? FAR_DELTA : (dnB - dB.w);

    const float sdA[4] = {sA.x, sA.y, sA.z, sA.w};
    const float sdB[4] = {sB.x, sB.y, sB.z, sB.w};

    float tauA[4], trA[4], tauB[4], trB[4];
#pragma unroll
    for (int i = 0; i < 4; ++i) {
        // LaplaceCDF(-x, b), branchless: e = 0.5*exp(-|x|/b)
        //   x > 0 -> e ; x <= 0 -> 1 - e
        const float xa = sdA[i];
        const float xb = sdB[i];
        const float ea = 0.5f * __expf(-fabsf(xa) * INV_BETA);
        const float eb = 0.5f * __expf(-fabsf(xb) * INV_BETA);
        const float cdfa = (xa > 0.0f) ? ea : (1.0f - ea);
        const float cdfb = (xb > 0.0f) ? eb : (1.0f - eb);
        tauA[i] = (RENDER_ALPHA * cdfa) * delA[i];
        tauB[i] = (RENDER_ALPHA * cdfb) * delB[i];
        trA[i]  = 1.0f - __expf(-tauA[i] + RENDER_EPS);
        trB[i]  = 1.0f - __expf(-tauB[i] + RENDER_EPS);
    }

    // Per-lane inclusive cumsum of the 4 taus (both rays).
    const float a0 = tauA[0], a1 = a0 + tauA[1], a2 = a1 + tauA[2], a3 = a2 + tauA[3];
    const float b0 = tauB[0], b1 = b0 + tauB[1], b2 = b1 + tauB[2], b3 = b2 + tauB[3];

    // Interleaved warp inclusive scans (ILP=2 across the shfl chain).
    float inA = a3, inB = b3;
#pragma unroll
    for (int off = 1; off < 32; off <<= 1) {
        const float va = __shfl_up_sync(0xffffffffu, inA, off);
        const float vb = __shfl_up_sync(0xffffffffu, inB, off);
        if (lane >= off) { inA += va; inB += vb; }
    }
    // Exclusive prefix = previous lane's inclusive value. Do NOT compute as
    // (incl - c3): lane 31's c3 holds the 1e10 far-delta tau and the
    // subtraction catastrophically cancels (R1/R2 rel_err=0.33 bug).
    float pA = __shfl_up_sync(0xffffffffu, inA, 1);
    float pB = __shfl_up_sync(0xffffffffu, inB, 1);
    if (lane == 0) { pA = 0.0f; pB = 0.0f; }

    const float wA0 = __expf(-(pA + a0)) * trA[0];
    const float wA1 = __expf(-(pA + a1)) * trA[1];
    const float wA2 = __expf(-(pA + a2)) * trA[2];
    const float wA3 = __expf(-(pA + a3)) * trA[3];
    const float wB0 = __expf(-(pB + b0)) * trB[0];
    const float wB1 = __expf(-(pB + b1)) * trB[1];
    const float wB2 = __expf(-(pB + b2)) * trB[2];
    const float wB3 = __expf(-(pB + b3)) * trB[3];

    // sample0=(ca.x,ca.y,ca.z) sample1=(ca.w,cb.x,cb.y)
    // sample2=(cb.z,cb.w,cc.x) sample3=(cc.y,cc.z,cc.w)
    float rA = wA0 * caA.x + wA1 * caA.w + wA2 * cbA.z + wA3 * ccA.y;
    float gA = wA0 * caA.y + wA1 * cbA.x + wA2 * cbA.w + wA3 * ccA.z;
    float bA = wA0 * caA.z + wA1 * cbA.y + wA2 * ccA.x + wA3 * ccA.w;
    float rB = wB0 * caB.x + wB1 * caB.w + wB2 * cbB.z + wB3 * ccB.y;
    float gB = wB0 * caB.y + wB1 * cbB.x + wB2 * cbB.w + wB3 * ccB.z;
    float bB = wB0 * caB.z + wB1 * cbB.y + wB2 * ccB.x + wB3 * ccB.w;

    // Interleaved warp reductions (6 values, ILP across shfl chain).
#pragma unroll
    for (int off = 16; off > 0; off >>= 1) {
        rA += __shfl_xor_sync(0xffffffffu, rA, off);
        gA += __shfl_xor_sync(0xffffffffu, gA, off);
        bA += __shfl_xor_sync(0xffffffffu, bA, off);
        rB += __shfl_xor_sync(0xffffffffu, rB, off);
        gB += __shfl_xor_sync(0xffffffffu, gB, off);
        bB += __shfl_xor_sync(0xffffffffu, bB, off);
    }

    if (lane == 0) {
        out[rayA * 3 + 0] = rA;
        out[rayA * 3 + 1] = gA;
        out[rayA * 3 + 2] = bA;
        if (rayB < N) {
            out[rayB * 3 + 0] = rB;
            out[rayB * 3 + 1] = gB;
            out[rayB * 3 + 2] = bB;
        }
    }
}

extern "C" void kernel_launch(void* const* d_in, const int* in_sizes, int n_in,
                              void* d_out, int out_size)
{
    // Identify buffers defensively by size. color is [N,128,3] -> uniquely 3x
    // larger than sdf/depth ([N,128] each).
    int ic = 0;
    for (int i = 1; i < n_in; ++i)
        if (in_sizes[i] > in_sizes[ic]) ic = i;

    int ia, ib;  // the two equal-size buffers, in index order
    if (ic == 0)      { ia = 1; ib = 2; }
    else if (ic == 1) { ia = 0; ib = 2; }
    else              { ia = 0; ib = 1; }

    int is, id;  // sdf index, depth index
    if (ic == 0) {
        // color first => name-sorted metadata (color, depth_values, sdf)
        id = ia; is = ib;
    } else {
        // insertion order (sdf, color, depth_values)
        is = ia; id = ib;
    }

    const float* sdf   = (const float*)d_in[is];
    const float* color = (const float*)d_in[ic];
    const float* depth = (const float*)d_in[id];
    float* out = (float*)d_out;

    const int N = out_size / 3;                     // 65536 rays
    const int raysPerBlock = 16;                    // 8 warps x 2 rays
    const int blocks = (N + raysPerBlock - 1) / raysPerBlock;
    volume_sdf_render_kernel<<<blocks, 256>>>(sdf, color, depth, out, N);
}

// round 9
// speedup vs baseline: 1.2067x; 1.2067x over previous
#include <cuda_runtime.h>
#include <cuda_bf16.h>

// VolumeSDF renderer: one warp per ray, 4 samples per lane.
// out[n] = sum_s T_s * (1 - exp(-tau_s + eps)) * color[n,s,:]
//   density = ALPHA * LaplaceCDF(-sdf; BETA)
//   tau_s   = density_s * delta_s,  delta = diff(depth), last = 1e10
//   T_s     = exp(-inclusive_cumsum(tau)_s)
//
// Bandwidth optimization: lanes whose exclusive prefix cum exceeds CUM_SKIP
// contribute at most exp(-CUM_SKIP) total weight (weights telescope), so their
// color loads are skipped entirely. Skipped lanes are the contiguous tail of
// the warp -> remaining loads stay coalesced; unrequested sectors save DRAM.

#define RENDER_ALPHA 10.0f
#define INV_BETA     20.0f      // 1 / 0.05
#define RENDER_EPS   1e-10f
#define FAR_DELTA    1e10f
#define CUM_SKIP     13.0f      // exp(-13) = 2.3e-6 abs-error bound on tail

__global__ __launch_bounds__(256)
void volume_sdf_render_kernel(const float* __restrict__ sdf,
                              const float* __restrict__ color,
                              const float* __restrict__ depth,
                              float* __restrict__ out,
                              int N)
{
    const int gtid = blockIdx.x * blockDim.x + threadIdx.x;
    const int ray  = gtid >> 5;          // one warp per ray
    const int lane = threadIdx.x & 31;
    if (ray >= N) return;

    const int S = 128;
    const long long base = (long long)ray * S + lane * 4;

    // Coalesced vector loads: 4 consecutive samples per lane.
    const float4 s4 = *reinterpret_cast<const float4*>(sdf   + base);
    const float4 d4 = *reinterpret_cast<const float4*>(depth + base);

    // Deltas. depth[4l+4] lives in the next lane's d4.x.
    const float dnext = __shfl_down_sync(0xffffffffu, d4.x, 1);
    float del[4];
    del[0] = d4.y - d4.x;
    del[1] = d4.z - d4.y;
    del[2] = d4.w - d4.z;
    del[3] = (lane == 31) ? FAR_DELTA : (dnext - d4.w);

    const float sd[4] = {s4.x, s4.y, s4.z, s4.w};

    float tau[4], trans[4];
#pragma unroll
    for (int i = 0; i < 4; ++i) {
        // LaplaceCDF(-x, b), branchless: e = 0.5*exp(-|x|/b)
        //   x > 0 -> e ; x <= 0 -> 1 - e
        const float x = sd[i];
        const float e = 0.5f * __expf(-fabsf(x) * INV_BETA);
        const float cdf = (x > 0.0f) ? e : (1.0f - e);
        tau[i]   = (RENDER_ALPHA * cdf) * del[i];
        trans[i] = 1.0f - __expf(-tau[i] + RENDER_EPS);
    }

    // Per-lane inclusive cumsum of the 4 taus.
    const float c0 = tau[0];
    const float c1 = c0 + tau[1];
    const float c2 = c1 + tau[2];
    const float c3 = c2 + tau[3];

    // Warp inclusive scan of lane totals.
    float incl = c3;
#pragma unroll
    for (int off = 1; off < 32; off <<= 1) {
        const float v = __shfl_up_sync(0xffffffffu, incl, off);
        if (lane >= off) incl += v;
    }
    // Exclusive prefix = previous lane's inclusive value. Do NOT compute it as
    // (incl - c3): lane 31's c3 contains the 1e10 far-delta tau and the
    // subtraction catastrophically cancels (R1/R2 rel_err=0.33 bug).
    float prefix = __shfl_up_sync(0xffffffffu, incl, 1);
    if (lane == 0) prefix = 0.0f;

    float r = 0.0f, g = 0.0f, b = 0.0f;

    // Every weight of this lane is <= exp(-prefix); the whole remaining tail
    // of the ray sums to <= exp(-prefix) as well. Skip the color loads when
    // that bound is below ~2e-6 (abs) -- saves ~40% of color DRAM traffic.
    if (prefix < CUM_SKIP) {
        const float w0 = __expf(-(prefix + c0)) * trans[0];
        const float w1 = __expf(-(prefix + c1)) * trans[1];
        const float w2 = __expf(-(prefix + c2)) * trans[2];
        const float w3 = __expf(-(prefix + c3)) * trans[3];

        // Color: 12 consecutive floats per lane (48 B, 16B-aligned) -> 3x float4.
        const long long cbase = base * 3;
        const float4 ca = *reinterpret_cast<const float4*>(color + cbase);
        const float4 cb = *reinterpret_cast<const float4*>(color + cbase + 4);
        const float4 cc = *reinterpret_cast<const float4*>(color + cbase + 8);
        // sample0=(ca.x,ca.y,ca.z) sample1=(ca.w,cb.x,cb.y)
        // sample2=(cb.z,cb.w,cc.x) sample3=(cc.y,cc.z,cc.w)
        r = w0 * ca.x + w1 * ca.w + w2 * cb.z + w3 * cc.y;
        g = w0 * ca.y + w1 * cb.x + w2 * cb.w + w3 * cc.z;
        b = w0 * ca.z + w1 * cb.y + w2 * cc.x + w3 * cc.w;
    }

    // Warp reduction over lanes (samples).
#pragma unroll
    for (int off = 16; off > 0; off >>= 1) {
        r += __shfl_xor_sync(0xffffffffu, r, off);
        g += __shfl_xor_sync(0xffffffffu, g, off);
        b += __shfl_xor_sync(0xffffffffu, b, off);
    }

    if (lane == 0) {
        out[ray * 3 + 0] = r;
        out[ray * 3 + 1] = g;
        out[ray * 3 + 2] = b;
    }
}

extern "C" void kernel_launch(void* const* d_in, const int* in_sizes, int n_in,
                              void* d_out, int out_size)
{
    // Identify buffers defensively by size. color is [N,128,3] -> uniquely 3x
    // larger than sdf/depth ([N,128] each).
    int ic = 0;
    for (int i = 1; i < n_in; ++i)
        if (in_sizes[i] > in_sizes[ic]) ic = i;

    int ia, ib;  // the two equal-size buffers, in index order
    if (ic == 0)      { ia = 1; ib = 2; }
    else if (ic == 1) { ia = 0; ib = 2; }
    else              { ia = 0; ib = 1; }

    int is, id;  // sdf index, depth index
    if (ic == 0) {
        // color first => name-sorted metadata (color, depth_values, sdf)
        id = ia; is = ib;
    } else {
        // insertion order (sdf, color, depth_values)
        is = ia; id = ib;
    }

    const float* sdf   = (const float*)d_in[is];
    const float* color = (const float*)d_in[ic];
    const float* depth = (const float*)d_in[id];
    float* out = (float*)d_out;

    const int N = out_size / 3;                   // 65536 rays
    const int threads = 256;                      // 8 warps = 8 rays / block
    const int blocks  = (N * 32 + threads - 1) / threads;
    volume_sdf_render_kernel<<<blocks, threads>>>(sdf, color, depth, out, N);
}

// round 10
// speedup vs baseline: 1.3005x; 1.0777x over previous
#include <cuda_runtime.h>
#include <cuda_bf16.h>

// VolumeSDF renderer: one warp per ray, 4 samples per lane.
// out[n] = sum_s T_s * (1 - exp(-tau_s + eps)) * color[n,s,:]
//   density = ALPHA * LaplaceCDF(-sdf; BETA)
//   tau_s   = density_s * delta_s,  delta = diff(depth), last = 1e10
//   T_s     = exp(-inclusive_cumsum(tau)_s)
//
// Bandwidth optimization: the tail weight sum past prefix p telescopes to
// <= exp(-p), so lanes with prefix >= CUM_SKIP skip their color loads.
// Lanes 0-15 load color UNCONDITIONALLY and front-batched with sdf/depth:
// cum essentially never crosses CUM_SKIP before sample 64, so these loads
// are free to hoist, restoring MLP before the scan (fixes R8's issue dip).

#define RENDER_ALPHA 10.0f
#define INV_BETA     20.0f      // 1 / 0.05
#define RENDER_EPS   1e-10f
#define FAR_DELTA    1e10f
#define CUM_SKIP     9.5f       // exp(-9.5) = 7.5e-5 abs tail bound

__global__ __launch_bounds__(256)
void volume_sdf_render_kernel(const float* __restrict__ sdf,
                              const float* __restrict__ color,
                              const float* __restrict__ depth,
                              float* __restrict__ out,
                              int N)
{
    const int gtid = blockIdx.x * blockDim.x + threadIdx.x;
    const int ray  = gtid >> 5;          // one warp per ray
    const int lane = threadIdx.x & 31;
    if (ray >= N) return;

    const int S = 128;
    const long long base  = (long long)ray * S + lane * 4;
    const long long cbase = base * 3;
    const bool early = (lane < 16);

    // Coalesced vector loads: 4 consecutive samples per lane.
    const float4 s4 = *reinterpret_cast<const float4*>(sdf   + base);
    const float4 d4 = *reinterpret_cast<const float4*>(depth + base);

    // Front-batch color for the first half of the warp (always needed).
    float4 ca, cb, cc;
    if (early) {
        ca = *reinterpret_cast<const float4*>(color + cbase);
        cb = *reinterpret_cast<const float4*>(color + cbase + 4);
        cc = *reinterpret_cast<const float4*>(color + cbase + 8);
    }

    // Deltas. depth[4l+4] lives in the next lane's d4.x.
    const float dnext = __shfl_down_sync(0xffffffffu, d4.x, 1);
    float del[4];
    del[0] = d4.y - d4.x;
    del[1] = d4.z - d4.y;
    del[2] = d4.w - d4.z;
    del[3] = (lane == 31) ? FAR_DELTA : (dnext - d4.w);

    const float sd[4] = {s4.x, s4.y, s4.z, s4.w};

    float tau[4], trans[4];
#pragma unroll
    for (int i = 0; i < 4; ++i) {
        // LaplaceCDF(-x, b), branchless: e = 0.5*exp(-|x|/b)
        //   x > 0 -> e ; x <= 0 -> 1 - e
        const float x = sd[i];
        const float e = 0.5f * __expf(-fabsf(x) * INV_BETA);
        const float cdf = (x > 0.0f) ? e : (1.0f - e);
        tau[i]   = (RENDER_ALPHA * cdf) * del[i];
        trans[i] = 1.0f - __expf(-tau[i] + RENDER_EPS);
    }

    // Per-lane inclusive cumsum of the 4 taus.
    const float c0 = tau[0];
    const float c1 = c0 + tau[1];
    const float c2 = c1 + tau[2];
    const float c3 = c2 + tau[3];

    // Warp inclusive scan of lane totals.
    float incl = c3;
#pragma unroll
    for (int off = 1; off < 32; off <<= 1) {
        const float v = __shfl_up_sync(0xffffffffu, incl, off);
        if (lane >= off) incl += v;
    }
    // Exclusive prefix = previous lane's inclusive value. Do NOT compute it as
    // (incl - c3): lane 31's c3 contains the 1e10 far-delta tau and the
    // subtraction catastrophically cancels (R1/R2 rel_err=0.33 bug).
    float prefix = __shfl_up_sync(0xffffffffu, incl, 1);
    if (lane == 0) prefix = 0.0f;

    // Late lanes: load color only if the tail bound is non-negligible.
    const bool have = early || (prefix < CUM_SKIP);
    if (!early && have) {
        ca = *reinterpret_cast<const float4*>(color + cbase);
        cb = *reinterpret_cast<const float4*>(color + cbase + 4);
        cc = *reinterpret_cast<const float4*>(color + cbase + 8);
    }

    float r = 0.0f, g = 0.0f, b = 0.0f;
    if (have) {
        const float w0 = __expf(-(prefix + c0)) * trans[0];
        const float w1 = __expf(-(prefix + c1)) * trans[1];
        const float w2 = __expf(-(prefix + c2)) * trans[2];
        const float w3 = __expf(-(prefix + c3)) * trans[3];
        // sample0=(ca.x,ca.y,ca.z) sample1=(ca.w,cb.x,cb.y)
        // sample2=(cb.z,cb.w,cc.x) sample3=(cc.y,cc.z,cc.w)
        r = w0 * ca.x + w1 * ca.w + w2 * cb.z + w3 * cc.y;
        g = w0 * ca.y + w1 * cb.x + w2 * cb.w + w3 * cc.z;
        b = w0 * ca.z + w1 * cb.y + w2 * cc.x + w3 * cc.w;
    }

    // Warp reduction over lanes (samples).
#pragma unroll
    for (int off = 16; off > 0; off >>= 1) {
        r += __shfl_xor_sync(0xffffffffu, r, off);
        g += __shfl_xor_sync(0xffffffffu, g, off);
        b += __shfl_xor_sync(0xffffffffu, b, off);
    }

    if (lane == 0) {
        out[ray * 3 + 0] = r;
        out[ray * 3 + 1] = g;
        out[ray * 3 + 2] = b;
    }
}

extern "C" void kernel_launch(void* const* d_in, const int* in_sizes, int n_in,
                              void* d_out, int out_size)
{
    // Identify buffers defensively by size. color is [N,128,3] -> uniquely 3x
    // larger than sdf/depth ([N,128] each).
    int ic = 0;
    for (int i = 1; i < n_in; ++i)
        if (in_sizes[i] > in_sizes[ic]) ic = i;

    int ia, ib;  // the two equal-size buffers, in index order
    if (ic == 0)      { ia = 1; ib = 2; }
    else if (ic == 1) { ia = 0; ib = 2; }
    else              { ia = 0; ib = 1; }

    int is, id;  // sdf index, depth index
    if (ic == 0) {
        // color first => name-sorted metadata (color, depth_values, sdf)
        id = ia; is = ib;
    } else {
        // insertion order (sdf, color, depth_values)
        is = ia; id = ib;
    }

    const float* sdf   = (const float*)d_in[is];
    const float* color = (const float*)d_in[ic];
    const float* depth = (const float*)d_in[id];
    float* out = (float*)d_out;

    const int N = out_size / 3;                   // 65536 rays
    const int threads = 256;                      // 8 warps = 8 rays / block
    const int blocks  = (N * 32 + threads - 1) / threads;
    volume_sdf_render_kernel<<<blocks, threads>>>(sdf, color, depth, out, N);
}